// round 5
// baseline (speedup 1.0000x reference)
#include <cuda_runtime.h>
#include <cuda_fp16.h>
#include <cstdint>
#include <cstddef>

// ============================================================================
// Problem constants
// ============================================================================
#define R_DIM 32
#define I_DIM 256
#define O_DIM 256
#define K_MAIN (R_DIM * I_DIM)   // 8192
#define KP 8256                  // 8192 + 64 bias columns
#define NCH 129                  // KP / 64
#define M_TILE 128
#define N_TILE 128
#define THREADS 256

// SMEM layout (bytes, dynamic). Total 107520 -> 2 CTAs/SM fit.
#define XOFF 0                   // x tile fp16: 128 rows * 512B (swizzled)
#define E2OFF 65536              // e fp16 [row][r], row stride 68B: 128*68
#define BOFF  74752              // (1024-aligned) B stages: 2 * 16384
#define SMEM_TOTAL (BOFF + 2 * 16384)   // 107520

// Packed fp16 B matrix: [O_DIM][KP], B[o][r*256+i] = W[r][o][i]; bias at tail
__device__ __align__(128) __half g_Bh[O_DIM * KP];

// ============================================================================
// PTX helpers (plain sm_100-safe: mma.sync / ldmatrix / cp.async only)
// ============================================================================
__device__ __forceinline__ uint32_t smem_u32(const void* p) {
    uint32_t a;
    asm("{ .reg .u64 t; cvta.to.shared.u64 t, %1; cvt.u32.u64 %0, t; }"
        : "=r"(a) : "l"(p));
    return a;
}

#define LDSM_X4(r0, r1, r2, r3, addr) \
    asm volatile("ldmatrix.sync.aligned.m8n8.x4.shared.b16 {%0,%1,%2,%3}, [%4];" \
        : "=r"(r0), "=r"(r1), "=r"(r2), "=r"(r3) : "r"(addr))

#define MMA16816(d, a, b) \
    asm volatile("mma.sync.aligned.m16n8k16.row.col.f32.f16.f16.f32 " \
        "{%0,%1,%2,%3}, {%4,%5,%6,%7}, {%8,%9}, {%0,%1,%2,%3};" \
        : "+f"((d)[0]), "+f"((d)[1]), "+f"((d)[2]), "+f"((d)[3]) \
        : "r"((a)[0]), "r"((a)[1]), "r"((a)[2]), "r"((a)[3]), \
          "r"((b)[0]), "r"((b)[1]))

#define CP_ASYNC16(dst, src) \
    asm volatile("cp.async.cg.shared.global [%0], [%1], 16;" \
        :: "r"(dst), "l"(src) : "memory")

#define CP_COMMIT() asm volatile("cp.async.commit_group;" ::: "memory")
#define CP_WAIT0()  asm volatile("cp.async.wait_group 0;" ::: "memory")

__device__ __forceinline__ uint32_t hmul2_u(uint32_t a, uint32_t s) {
    __half2 r = __hmul2(*reinterpret_cast<__half2*>(&a),
                        *reinterpret_cast<__half2*>(&s));
    return *reinterpret_cast<uint32_t*>(&r);
}

// ============================================================================
// Prep kernel: pack W [R,O,I] fp32 + b [R,O] fp32 -> g_Bh [O][KP] fp16
// ============================================================================
__global__ void LinearKG_prep_kernel(const float* __restrict__ W,
                                     const float* __restrict__ b) {
    int idx = blockIdx.x * blockDim.x + threadIdx.x;
    if (idx >= O_DIM * KP) return;
    int o = idx / KP;
    int k = idx - o * KP;
    float v;
    if (k < K_MAIN) {
        int r = k >> 8, i = k & 255;
        v = W[((size_t)r * O_DIM + o) * I_DIM + i];
    } else {
        int r = k - K_MAIN;
        v = (r < R_DIM) ? b[r * O_DIM + o] : 0.0f;
    }
    g_Bh[idx] = __float2half(v);
}

// ============================================================================
// Main fused GEMM: y[128x128 tile] = A @ B^T, A built on the fly from x,e.
// q-outer / r-inner chunk order: x fragments live in registers for 32 chunks,
// only B ldsm + e rescale + MMA in the hot loop. 8 warps 4Mx2N, 2 CTAs/SM.
// Chunk sequence: s in [0,128); q=s>>5, r=s&31 -> chunk j=4r+q; s=128 -> bias.
// ============================================================================
__global__ void __launch_bounds__(THREADS, 2)
LinearKG_main_kernel(const float* __restrict__ xg,
                     const float* __restrict__ eg,
                     float* __restrict__ out,
                     int n_nodes) {
    extern __shared__ __align__(1024) char smem[];
    const uint32_t sb = smem_u32(smem);
    const int tid = threadIdx.x;
    const int wid = tid >> 5;
    const int lid = tid & 31;
    const int row_base = blockIdx.x * M_TILE;
    const int o_base = blockIdx.y * N_TILE;
    const int warpM = (wid & 3) << 5;    // 0,32,64,96
    const int warpN = (wid >> 2) << 6;   // 0,64

    // ---- B prefetch: 128 rows x 128B per stage; 256 thr -> 64B each ----
    const int brow = tid >> 1;           // 0..127
    const int bq = tid & 1;              // 0..1
    const char* bsrc_row = reinterpret_cast<const char*>(g_Bh) +
                           ((size_t)(o_base + brow) * KP) * 2 + bq * 64;
    const uint32_t bdst_row = sb + BOFF + brow * 128;
    const int brow7 = brow & 7;

#define ISSUE_B(jj, stg) do { \
        const char* _s = bsrc_row + (size_t)(jj) * 128; \
        uint32_t _d = bdst_row + (stg) * 16384; \
        _Pragma("unroll") \
        for (int _c = 0; _c < 4; _c++) { \
            int _c16 = bq * 4 + _c; \
            CP_ASYNC16(_d + (((_c16) ^ brow7) << 4), _s + _c * 16); \
        } \
        CP_COMMIT(); \
    } while (0)

    // prologue: prefetch chunk for s=0 (j=0) into stage 0
    ISSUE_B(0, 0);

    // ---- fill x tile (fp32 -> fp16, swizzled) + e tile ----
    {
        const float4* x4 = reinterpret_cast<const float4*>(xg);
        #pragma unroll
        for (int it = 0; it < 16; it++) {
            int v = tid + it * THREADS;          // 0..4095
            int row = v >> 5, c = v & 31;
            int gr = row_base + row;
            float4 f0 = make_float4(0.f, 0.f, 0.f, 0.f), f1 = f0;
            if (gr < n_nodes) {
                f0 = x4[(size_t)gr * 64 + c * 2];
                f1 = x4[(size_t)gr * 64 + c * 2 + 1];
            }
            __half2 h0 = __floats2half2_rn(f0.x, f0.y);
            __half2 h1 = __floats2half2_rn(f0.z, f0.w);
            __half2 h2 = __floats2half2_rn(f1.x, f1.y);
            __half2 h3 = __floats2half2_rn(f1.z, f1.w);
            uint4 u;
            u.x = *reinterpret_cast<uint32_t*>(&h0);
            u.y = *reinterpret_cast<uint32_t*>(&h1);
            u.z = *reinterpret_cast<uint32_t*>(&h2);
            u.w = *reinterpret_cast<uint32_t*>(&h3);
            *reinterpret_cast<uint4*>(smem + XOFF + row * 512 +
                                      ((c ^ (row & 7)) << 4)) = u;
        }
        __half* e2w = reinterpret_cast<__half*>(smem + E2OFF);
        #pragma unroll
        for (int it = 0; it < 16; it++) {
            int v = tid + it * THREADS;          // 0..4095
            int row = v >> 5, r = v & 31;
            int gr = row_base + row;
            float ev = (gr < n_nodes) ? eg[(size_t)gr * R_DIM + r] : 0.0f;
            e2w[row * 34 + r] = __float2half(ev);
        }
    }
    __syncthreads();   // x/e tiles visible to all warps (xraw loads need this)

    const __half* e2h = reinterpret_cast<const __half*>(smem + E2OFF);

    // ---- per-thread fragment addressing ----
    const int g = lid >> 3;
    const int l7 = lid & 7;
    const int a_moff = (g & 1) * 8;
    const int a_koff = g >> 1;
    const int b_noff = (g >> 1) * 8;
    const int b_koff = g & 1;

    uint32_t aBase[2]; int aXor[2];
    #pragma unroll
    for (int mt = 0; mt < 2; mt++) {
        int mrow = warpM + mt * 16 + a_moff + l7;
        aBase[mt] = sb + XOFF + mrow * 512;
        aXor[mt] = mrow & 7;
    }
    uint32_t bBase[4]; int bXor[4];
    #pragma unroll
    for (int bt = 0; bt < 4; bt++) {
        int nrow = warpN + bt * 16 + b_noff + l7;
        bBase[bt] = sb + BOFF + nrow * 128;
        bXor[bt] = nrow & 7;
    }
    const int frow = lid >> 2;
    const int fcol = (lid & 3) * 2;
    const int erow0 = (warpM + frow) * 34;       // e2h row offsets (halves)
    const int erow1 = (warpM + 8 + frow) * 34;

    float acc[2][8][4];
    #pragma unroll
    for (int mt = 0; mt < 2; mt++)
        #pragma unroll
        for (int nt = 0; nt < 8; nt++)
            #pragma unroll
            for (int q = 0; q < 4; q++) acc[mt][nt][q] = 0.0f;

    // ---- main loops: q outer (x frags in regs), r inner (B streams) ----
    for (int q = 0; q < 4; q++) {
        // load raw x fragments for this q: 8 ldsm.x4, live for 32 chunks
        uint32_t xraw[2][4][4];
        #pragma unroll
        for (int mt = 0; mt < 2; mt++)
            #pragma unroll
            for (int ks = 0; ks < 4; ks++) {
                int kc = q * 8 + ks * 2 + a_koff;
                uint32_t ad = aBase[mt] + ((kc ^ aXor[mt]) << 4);
                LDSM_X4(xraw[mt][ks][0], xraw[mt][ks][1],
                        xraw[mt][ks][2], xraw[mt][ks][3], ad);
            }

        for (int rr = 0; rr < 32; rr++) {
            const int s = q * 32 + rr;
            const int stage = s & 1;

            CP_WAIT0();          // this chunk landed (issued 1 iter ago)
            __syncthreads();     // publish stage; also: all warps done s-1

            // prefetch next chunk in sequence into the stage freed at s-1
            if (rr < 31)      ISSUE_B(4 * rr + q + 4, stage ^ 1);
            else if (q < 3)   ISSUE_B(q + 1, stage ^ 1);
            else              ISSUE_B(128, stage ^ 1);

            // e scales for r = rr
            uint32_t ez0[2], ez1[2];
            #pragma unroll
            for (int mt = 0; mt < 2; mt++) {
                __half h0 = e2h[erow0 + mt * 16 * 34 + rr];
                __half h1 = e2h[erow1 + mt * 16 * 34 + rr];
                __half2 p0 = __half2half2(h0);
                __half2 p1 = __half2half2(h1);
                ez0[mt] = *reinterpret_cast<uint32_t*>(&p0);
                ez1[mt] = *reinterpret_cast<uint32_t*>(&p1);
            }

            const uint32_t bst = stage * 16384;
            #pragma unroll
            for (int ks = 0; ks < 4; ks++) {
                uint32_t a[2][4];
                #pragma unroll
                for (int mt = 0; mt < 2; mt++) {
                    a[mt][0] = hmul2_u(xraw[mt][ks][0], ez0[mt]);
                    a[mt][1] = hmul2_u(xraw[mt][ks][1], ez1[mt]);
                    a[mt][2] = hmul2_u(xraw[mt][ks][2], ez0[mt]);
                    a[mt][3] = hmul2_u(xraw[mt][ks][3], ez1[mt]);
                }
                #pragma unroll
                for (int h = 0; h < 2; h++) {
                    uint32_t bf[4][2];
                    #pragma unroll
                    for (int p = 0; p < 2; p++) {
                        int bt = h * 2 + p;
                        int kc = ks * 2 + b_koff;
                        uint32_t bd = bBase[bt] + bst + ((kc ^ bXor[bt]) << 4);
                        uint32_t r0, r1, r2, r3;
                        LDSM_X4(r0, r1, r2, r3, bd);
                        bf[p * 2][0] = r0;     bf[p * 2][1] = r1;
                        bf[p * 2 + 1][0] = r2; bf[p * 2 + 1][1] = r3;
                    }
                    #pragma unroll
                    for (int mt = 0; mt < 2; mt++)
                        #pragma unroll
                        for (int nt = 0; nt < 4; nt++)
                            MMA16816(acc[mt][h * 4 + nt], a[mt], bf[nt]);
                }
            }
        }
    }

    // ---- bias chunk (s=128, stage 0): A[m,k] = e[m,k], k<32 ----
    {
        CP_WAIT0();
        __syncthreads();
        const uint32_t bst = 0;
        #pragma unroll
        for (int ks = 0; ks < 2; ks++) {
            const int k0 = ks * 16 + fcol;
            uint32_t a[2][4];
            #pragma unroll
            for (int mt = 0; mt < 2; mt++) {
                a[mt][0] = *reinterpret_cast<const uint32_t*>(
                    e2h + erow0 + mt * 16 * 34 + k0);
                a[mt][1] = *reinterpret_cast<const uint32_t*>(
                    e2h + erow1 + mt * 16 * 34 + k0);
                a[mt][2] = *reinterpret_cast<const uint32_t*>(
                    e2h + erow0 + mt * 16 * 34 + k0 + 8);
                a[mt][3] = *reinterpret_cast<const uint32_t*>(
                    e2h + erow1 + mt * 16 * 34 + k0 + 8);
            }
            #pragma unroll
            for (int h = 0; h < 2; h++) {
                uint32_t bf[4][2];
                #pragma unroll
                for (int p = 0; p < 2; p++) {
                    int bt = h * 2 + p;
                    int kc = ks * 2 + b_koff;
                    uint32_t bd = bBase[bt] + bst + ((kc ^ bXor[bt]) << 4);
                    uint32_t r0, r1, r2, r3;
                    LDSM_X4(r0, r1, r2, r3, bd);
                    bf[p * 2][0] = r0;     bf[p * 2][1] = r1;
                    bf[p * 2 + 1][0] = r2; bf[p * 2 + 1][1] = r3;
                }
                #pragma unroll
                for (int mt = 0; mt < 2; mt++)
                    #pragma unroll
                    for (int nt = 0; nt < 4; nt++)
                        MMA16816(acc[mt][h * 4 + nt], a[mt], bf[nt]);
            }
        }
    }

    // ---- epilogue: store fp32 accumulators ----
    #pragma unroll
    for (int mt = 0; mt < 2; mt++) {
        int r0 = row_base + warpM + mt * 16 + frow;
        int r1 = r0 + 8;
        #pragma unroll
        for (int nt = 0; nt < 8; nt++) {
            int col = o_base + warpN + nt * 8 + fcol;
            if (r0 < n_nodes) {
                float2 v = make_float2(acc[mt][nt][0], acc[mt][nt][1]);
                *reinterpret_cast<float2*>(out + (size_t)r0 * O_DIM + col) = v;
            }
            if (r1 < n_nodes) {
                float2 v = make_float2(acc[mt][nt][2], acc[mt][nt][3]);
                *reinterpret_cast<float2*>(out + (size_t)r1 * O_DIM + col) = v;
            }
        }
    }
#undef ISSUE_B
}

// ============================================================================
// Launch
// ============================================================================
extern "C" void kernel_launch(void* const* d_in, const int* in_sizes, int n_in,
                              void* d_out, int out_size) {
    const float* x = (const float*)d_in[0];   // [N, 256]
    const float* e = (const float*)d_in[1];   // [N, 32]
    const float* W = (const float*)d_in[2];   // [32, 256, 256]
    const float* b = (const float*)d_in[3];   // [32, 256]
    float* out = (float*)d_out;               // [N, 256]

    int n_nodes = in_sizes[0] / I_DIM;

    int prep_total = O_DIM * KP;
    LinearKG_prep_kernel<<<(prep_total + 255) / 256, 256>>>(W, b);

    cudaFuncSetAttribute(LinearKG_main_kernel,
                         cudaFuncAttributeMaxDynamicSharedMemorySize, SMEM_TOTAL);
    dim3 grid((n_nodes + M_TILE - 1) / M_TILE, O_DIM / N_TILE);
    LinearKG_main_kernel<<<grid, THREADS, SMEM_TOTAL>>>(x, e, out, n_nodes);
}

// round 6
// speedup vs baseline: 1.0367x; 1.0367x over previous
#include <cuda_runtime.h>
#include <cuda_fp16.h>
#include <cstdint>
#include <cstddef>

// ============================================================================
// Problem constants
// ============================================================================
#define R_DIM 32
#define I_DIM 256
#define O_DIM 256
#define K_MAIN (R_DIM * I_DIM)   // 8192
#define KP 8256                  // 8192 + 64 bias columns
#define NCH 129                  // KP / 64
#define M_TILE 128
#define N_TILE 64
#define THREADS 256
#define STAGE_BYTES 8192         // 64 B-rows x 128B

// SMEM layout (bytes, dynamic). Total 107520 -> 2 CTAs/SM.
#define XOFF 0                   // x tile fp16: 128 rows * 512B (swizzled)
#define E2OFF 65536              // e fp16 [row][r], row stride 68B: 128*68
#define BOFF  74752              // (1024-aligned) B stages: 4 * 8192
#define SMEM_TOTAL (BOFF + 4 * STAGE_BYTES)   // 107520

// Packed fp16 B matrix: [O_DIM][KP], B[o][r*256+i] = W[r][o][i]; bias at tail
__device__ __align__(128) __half g_Bh[O_DIM * KP];

// ============================================================================
// PTX helpers (plain sm_100-safe: mma.sync / ldmatrix / cp.async only)
// ============================================================================
__device__ __forceinline__ uint32_t smem_u32(const void* p) {
    uint32_t a;
    asm("{ .reg .u64 t; cvta.to.shared.u64 t, %1; cvt.u32.u64 %0, t; }"
        : "=r"(a) : "l"(p));
    return a;
}

#define LDSM_X4(r0, r1, r2, r3, addr) \
    asm volatile("ldmatrix.sync.aligned.m8n8.x4.shared.b16 {%0,%1,%2,%3}, [%4];" \
        : "=r"(r0), "=r"(r1), "=r"(r2), "=r"(r3) : "r"(addr))

#define MMA16816(d, a, b) \
    asm volatile("mma.sync.aligned.m16n8k16.row.col.f32.f16.f16.f32 " \
        "{%0,%1,%2,%3}, {%4,%5,%6,%7}, {%8,%9}, {%0,%1,%2,%3};" \
        : "+f"((d)[0]), "+f"((d)[1]), "+f"((d)[2]), "+f"((d)[3]) \
        : "r"((a)[0]), "r"((a)[1]), "r"((a)[2]), "r"((a)[3]), \
          "r"((b)[0]), "r"((b)[1]))

#define CP_ASYNC16(dst, src) \
    asm volatile("cp.async.cg.shared.global [%0], [%1], 16;" \
        :: "r"(dst), "l"(src) : "memory")

#define CP_COMMIT() asm volatile("cp.async.commit_group;" ::: "memory")
#define CP_WAIT2()  asm volatile("cp.async.wait_group 2;" ::: "memory")

__device__ __forceinline__ uint32_t hmul2_u(uint32_t a, uint32_t s) {
    __half2 r = __hmul2(*reinterpret_cast<__half2*>(&a),
                        *reinterpret_cast<__half2*>(&s));
    return *reinterpret_cast<uint32_t*>(&r);
}

// ============================================================================
// Prep kernel: pack W [R,O,I] fp32 + b [R,O] fp32 -> g_Bh [O][KP] fp16
// ============================================================================
__global__ void LinearKG_prep_kernel(const float* __restrict__ W,
                                     const float* __restrict__ b) {
    int idx = blockIdx.x * blockDim.x + threadIdx.x;
    if (idx >= O_DIM * KP) return;
    int o = idx / KP;
    int k = idx - o * KP;
    float v;
    if (k < K_MAIN) {
        int r = k >> 8, i = k & 255;
        v = W[((size_t)r * O_DIM + o) * I_DIM + i];
    } else {
        int r = k - K_MAIN;
        v = (r < R_DIM) ? b[r * O_DIM + o] : 0.0f;
    }
    g_Bh[idx] = __float2half(v);
}

// ============================================================================
// Main fused GEMM: y[128x64 tile] = A @ B^T, A built on the fly from x,e.
// 8 warps 4Mx2N (warp tile 32x32), 2 CTAs/SM, 4-stage B ring at prefetch
// distance 3, one __syncthreads per chunk.
// ============================================================================
__global__ void __launch_bounds__(THREADS, 2)
LinearKG_main_kernel(const float* __restrict__ xg,
                     const float* __restrict__ eg,
                     float* __restrict__ out,
                     int n_nodes) {
    extern __shared__ __align__(1024) char smem[];
    const uint32_t sb = smem_u32(smem);
    const int tid = threadIdx.x;
    const int wid = tid >> 5;
    const int lid = tid & 31;
    const int row_base = blockIdx.x * M_TILE;
    const int o_base = blockIdx.y * N_TILE;
    const int warpM = (wid & 3) << 5;    // 0,32,64,96
    const int warpN = (wid >> 2) << 5;   // 0,32

    // ---- B prefetch: 64 rows x 128B per stage; 256 thr -> 32B each ----
    const int brow = tid >> 2;           // 0..63
    const int bq = tid & 3;              // 0..3
    const char* bsrc_row = reinterpret_cast<const char*>(g_Bh) +
                           ((size_t)(o_base + brow) * KP) * 2 + bq * 32;
    const uint32_t bdst_row = sb + BOFF + brow * 128;
    const int brow7 = brow & 7;

#define ISSUE_B(jj, stg) do { \
        const char* _s = bsrc_row + (size_t)(jj) * 128; \
        uint32_t _d = bdst_row + (stg) * STAGE_BYTES; \
        _Pragma("unroll") \
        for (int _c = 0; _c < 2; _c++) { \
            int _c16 = bq * 2 + _c; \
            CP_ASYNC16(_d + (((_c16) ^ brow7) << 4), _s + _c * 16); \
        } \
        CP_COMMIT(); \
    } while (0)

    // prologue: prefetch chunks 0..2 into stages 0..2
    ISSUE_B(0, 0);
    ISSUE_B(1, 1);
    ISSUE_B(2, 2);

    // ---- fill x tile (fp32 -> fp16, swizzled) + e tile ----
    {
        const float4* x4 = reinterpret_cast<const float4*>(xg);
        #pragma unroll
        for (int it = 0; it < 16; it++) {
            int v = tid + it * THREADS;          // 0..4095
            int row = v >> 5, c = v & 31;
            int gr = row_base + row;
            float4 f0 = make_float4(0.f, 0.f, 0.f, 0.f), f1 = f0;
            if (gr < n_nodes) {
                f0 = x4[(size_t)gr * 64 + c * 2];
                f1 = x4[(size_t)gr * 64 + c * 2 + 1];
            }
            __half2 h0 = __floats2half2_rn(f0.x, f0.y);
            __half2 h1 = __floats2half2_rn(f0.z, f0.w);
            __half2 h2 = __floats2half2_rn(f1.x, f1.y);
            __half2 h3 = __floats2half2_rn(f1.z, f1.w);
            uint4 u;
            u.x = *reinterpret_cast<uint32_t*>(&h0);
            u.y = *reinterpret_cast<uint32_t*>(&h1);
            u.z = *reinterpret_cast<uint32_t*>(&h2);
            u.w = *reinterpret_cast<uint32_t*>(&h3);
            *reinterpret_cast<uint4*>(smem + XOFF + row * 512 +
                                      ((c ^ (row & 7)) << 4)) = u;
        }
        __half* e2w = reinterpret_cast<__half*>(smem + E2OFF);
        #pragma unroll
        for (int it = 0; it < 16; it++) {
            int v = tid + it * THREADS;          // 0..4095
            int row = v >> 5, r = v & 31;
            int gr = row_base + row;
            float ev = (gr < n_nodes) ? eg[(size_t)gr * R_DIM + r] : 0.0f;
            e2w[row * 34 + r] = __float2half(ev);
        }
    }

    const __half* e2h = reinterpret_cast<const __half*>(smem + E2OFF);

    // ---- per-thread fragment addressing ----
    const int g = lid >> 3;
    const int l7 = lid & 7;
    const int a_moff = (g & 1) * 8;
    const int a_koff = g >> 1;
    const int b_noff = (g >> 1) * 8;
    const int b_koff = g & 1;

    uint32_t aBase[2]; int aXor[2];
    #pragma unroll
    for (int mt = 0; mt < 2; mt++) {
        int mrow = warpM + mt * 16 + a_moff + l7;
        aBase[mt] = sb + XOFF + mrow * 512;
        aXor[mt] = mrow & 7;
    }
    uint32_t bBase[2]; int bXor[2];
    #pragma unroll
    for (int bt = 0; bt < 2; bt++) {
        int nrow = warpN + bt * 16 + b_noff + l7;
        bBase[bt] = sb + BOFF + nrow * 128;
        bXor[bt] = nrow & 7;
    }
    const int frow = lid >> 2;
    const int fcol = (lid & 3) * 2;
    const int erow0 = (warpM + frow) * 34;
    const int erow1 = (warpM + 8 + frow) * 34;

    float acc[2][4][4];
    #pragma unroll
    for (int mt = 0; mt < 2; mt++)
        #pragma unroll
        for (int nt = 0; nt < 4; nt++)
            #pragma unroll
            for (int q = 0; q < 4; q++) acc[mt][nt][q] = 0.0f;

    uint32_t ez0[2], ez1[2];

    // ---- main loop: 129 chunks, 4-stage ring, distance-3 prefetch ----
    for (int j = 0; j < NCH; j++) {
        const int stage = j & 3;

        CP_WAIT2();              // commit #j (chunk j) landed
        __syncthreads();         // publish stage j; all warps done chunk j-1

        // refill the stage chunk j-1 just vacated (safe: after barrier)
        if (j + 3 < NCH) ISSUE_B(j + 3, (j + 3) & 3);
        else CP_COMMIT();        // empty group keeps wait accounting exact

        const uint32_t bst = stage * STAGE_BYTES;

        if (j < 128) {
            const int r = j >> 2;
            if ((j & 3) == 0) {
                #pragma unroll
                for (int mt = 0; mt < 2; mt++) {
                    __half h0 = e2h[erow0 + mt * 16 * 34 + r];
                    __half h1 = e2h[erow1 + mt * 16 * 34 + r];
                    __half2 p0 = __half2half2(h0);
                    __half2 p1 = __half2half2(h1);
                    ez0[mt] = *reinterpret_cast<uint32_t*>(&p0);
                    ez1[mt] = *reinterpret_cast<uint32_t*>(&p1);
                }
            }
            const int kcA = (j & 3) * 8;
            #pragma unroll
            for (int ks = 0; ks < 4; ks++) {
                uint32_t a[2][4];
                #pragma unroll
                for (int mt = 0; mt < 2; mt++) {
                    int kc = kcA + ks * 2 + a_koff;
                    uint32_t ad = aBase[mt] + ((kc ^ aXor[mt]) << 4);
                    LDSM_X4(a[mt][0], a[mt][1], a[mt][2], a[mt][3], ad);
                    a[mt][0] = hmul2_u(a[mt][0], ez0[mt]);
                    a[mt][1] = hmul2_u(a[mt][1], ez1[mt]);
                    a[mt][2] = hmul2_u(a[mt][2], ez0[mt]);
                    a[mt][3] = hmul2_u(a[mt][3], ez1[mt]);
                }
                uint32_t bf[4][2];
                #pragma unroll
                for (int bt = 0; bt < 2; bt++) {
                    int kc = ks * 2 + b_koff;
                    uint32_t bd = bBase[bt] + bst + ((kc ^ bXor[bt]) << 4);
                    uint32_t r0, r1, r2, r3;
                    LDSM_X4(r0, r1, r2, r3, bd);
                    bf[bt * 2][0] = r0;     bf[bt * 2][1] = r1;
                    bf[bt * 2 + 1][0] = r2; bf[bt * 2 + 1][1] = r3;
                }
                #pragma unroll
                for (int mt = 0; mt < 2; mt++)
                    #pragma unroll
                    for (int nt = 0; nt < 4; nt++)
                        MMA16816(acc[mt][nt], a[mt], bf[nt]);
            }
        } else {
            // bias chunk: A[m,k] = e[m,k] for k<32 (ksteps 0..1 only)
            #pragma unroll
            for (int ks = 0; ks < 2; ks++) {
                const int k0 = ks * 16 + fcol;
                uint32_t a[2][4];
                #pragma unroll
                for (int mt = 0; mt < 2; mt++) {
                    a[mt][0] = *reinterpret_cast<const uint32_t*>(
                        e2h + erow0 + mt * 16 * 34 + k0);
                    a[mt][1] = *reinterpret_cast<const uint32_t*>(
                        e2h + erow1 + mt * 16 * 34 + k0);
                    a[mt][2] = *reinterpret_cast<const uint32_t*>(
                        e2h + erow0 + mt * 16 * 34 + k0 + 8);
                    a[mt][3] = *reinterpret_cast<const uint32_t*>(
                        e2h + erow1 + mt * 16 * 34 + k0 + 8);
                }
                uint32_t bf[4][2];
                #pragma unroll
                for (int bt = 0; bt < 2; bt++) {
                    int kc = ks * 2 + b_koff;
                    uint32_t bd = bBase[bt] + bst + ((kc ^ bXor[bt]) << 4);
                    uint32_t r0, r1, r2, r3;
                    LDSM_X4(r0, r1, r2, r3, bd);
                    bf[bt * 2][0] = r0;     bf[bt * 2][1] = r1;
                    bf[bt * 2 + 1][0] = r2; bf[bt * 2 + 1][1] = r3;
                }
                #pragma unroll
                for (int mt = 0; mt < 2; mt++)
                    #pragma unroll
                    for (int nt = 0; nt < 4; nt++)
                        MMA16816(acc[mt][nt], a[mt], bf[nt]);
            }
        }
    }

    // ---- epilogue: store fp32 accumulators ----
    #pragma unroll
    for (int mt = 0; mt < 2; mt++) {
        int r0 = row_base + warpM + mt * 16 + frow;
        int r1 = r0 + 8;
        #pragma unroll
        for (int nt = 0; nt < 4; nt++) {
            int col = o_base + warpN + nt * 8 + fcol;
            if (r0 < n_nodes) {
                float2 v = make_float2(acc[mt][nt][0], acc[mt][nt][1]);
                *reinterpret_cast<float2*>(out + (size_t)r0 * O_DIM + col) = v;
            }
            if (r1 < n_nodes) {
                float2 v = make_float2(acc[mt][nt][2], acc[mt][nt][3]);
                *reinterpret_cast<float2*>(out + (size_t)r1 * O_DIM + col) = v;
            }
        }
    }
#undef ISSUE_B
}

// ============================================================================
// Launch
// ============================================================================
extern "C" void kernel_launch(void* const* d_in, const int* in_sizes, int n_in,
                              void* d_out, int out_size) {
    const float* x = (const float*)d_in[0];   // [N, 256]
    const float* e = (const float*)d_in[1];   // [N, 32]
    const float* W = (const float*)d_in[2];   // [32, 256, 256]
    const float* b = (const float*)d_in[3];   // [32, 256]
    float* out = (float*)d_out;               // [N, 256]

    int n_nodes = in_sizes[0] / I_DIM;

    int prep_total = O_DIM * KP;
    LinearKG_prep_kernel<<<(prep_total + 255) / 256, 256>>>(W, b);

    cudaFuncSetAttribute(LinearKG_main_kernel,
                         cudaFuncAttributeMaxDynamicSharedMemorySize, SMEM_TOTAL);
    dim3 grid((n_nodes + M_TILE - 1) / M_TILE, O_DIM / N_TILE);
    LinearKG_main_kernel<<<grid, THREADS, SMEM_TOTAL>>>(x, e, out, n_nodes);
}

// round 7
// speedup vs baseline: 1.4079x; 1.3580x over previous
#include <cuda_runtime.h>
#include <cuda_fp16.h>
#include <cstdint>
#include <cstddef>

// ============================================================================
// Problem constants
// ============================================================================
#define R_DIM 32
#define I_DIM 256
#define O_DIM 256
#define K_MAIN (R_DIM * I_DIM)   // 8192
#define NCH 129                  // 128 main chunks + 1 bias chunk
#define M_TILE 128
#define N_TILE 128
#define THREADS 256

// SMEM: x tile fp16 (128 rows * 512B, swizzled) + e fp16 [128][34]
#define XOFF 0
#define E2OFF 65536
#define SMEM_TOTAL (E2OFF + 8704)      // 74240 -> 2 CTAs/SM

// Packed B fragments, mma.sync-native layout:
// g_P[oh][j][ks][q][lane] : uint4.  oh = 64-wide O block (4), j = K chunk (129),
// ks = k-step (4), q = reg quad (4), lane = 0..31.
// u32 reg (q*4+c): nt = reg>>1, b = reg&1 ->
//   half2{ B[o = oh*64 + nt*8 + lane/4][k = j*64+ks*16+b*8+(lane%4)*2], B[o][k+1] }
#define P_U4_PER_KS  128
#define P_U4_PER_J   (4 * P_U4_PER_KS)
#define P_U4_PER_OH  (NCH * P_U4_PER_J)
__device__ __align__(128) uint4 g_P[4 * P_U4_PER_OH];   // 4.2 MB, L2-resident

// ============================================================================
// PTX helpers (plain sm_100-safe)
// ============================================================================
__device__ __forceinline__ uint32_t smem_u32(const void* p) {
    uint32_t a;
    asm("{ .reg .u64 t; cvta.to.shared.u64 t, %1; cvt.u32.u64 %0, t; }"
        : "=r"(a) : "l"(p));
    return a;
}

#define LDSM_X4(r0, r1, r2, r3, addr) \
    asm volatile("ldmatrix.sync.aligned.m8n8.x4.shared.b16 {%0,%1,%2,%3}, [%4];" \
        : "=r"(r0), "=r"(r1), "=r"(r2), "=r"(r3) : "r"(addr))

#define MMA16816(d, a, b0, b1) \
    asm volatile("mma.sync.aligned.m16n8k16.row.col.f32.f16.f16.f32 " \
        "{%0,%1,%2,%3}, {%4,%5,%6,%7}, {%8,%9}, {%0,%1,%2,%3};" \
        : "+f"((d)[0]), "+f"((d)[1]), "+f"((d)[2]), "+f"((d)[3]) \
        : "r"((a)[0]), "r"((a)[1]), "r"((a)[2]), "r"((a)[3]), \
          "r"(b0), "r"(b1))

__device__ __forceinline__ uint32_t hmul2_u(uint32_t a, uint32_t s) {
    __half2 r = __hmul2(*reinterpret_cast<__half2*>(&a),
                        *reinterpret_cast<__half2*>(&s));
    return *reinterpret_cast<uint32_t*>(&r);
}

// ============================================================================
// Prep kernel: W [R,O,I] fp32 + b [R,O] fp32 -> fragment-packed fp16 g_P
// ============================================================================
__global__ void LinearKG_prep_kernel(const float* __restrict__ W,
                                     const float* __restrict__ b) {
    int idx = blockIdx.x * blockDim.x + threadIdx.x;        // u32 index
    if (idx >= 4 * P_U4_PER_OH * 4) return;
    int c = idx & 3;
    int u4 = idx >> 2;
    int lane = u4 & 31;
    int q = (u4 >> 5) & 3;
    int rest = u4 >> 7;
    int ks = rest & 3;
    rest >>= 2;
    int j = rest % NCH;
    int oh = rest / NCH;

    int reg = q * 4 + c;
    int nt = reg >> 1;
    int bb = reg & 1;
    int o = oh * 64 + nt * 8 + (lane >> 2);
    int k = j * 64 + ks * 16 + bb * 8 + (lane & 3) * 2;

    float v0, v1;
    if (k < K_MAIN) {
        int r = k >> 8, i = k & 255;
        const float* wp = W + ((size_t)r * O_DIM + o) * I_DIM + i;
        v0 = wp[0];
        v1 = wp[1];                       // i, i+1 stay in same r (i even < 255)
    } else {
        int r = k - K_MAIN;
        v0 = (r < R_DIM) ? b[r * O_DIM + o] : 0.0f;
        v1 = (r + 1 < R_DIM) ? b[(r + 1) * O_DIM + o] : 0.0f;
    }
    __half2 h = __floats2half2_rn(v0, v1);
    reinterpret_cast<uint32_t*>(g_P)[idx] = *reinterpret_cast<uint32_t*>(&h);
}

// ============================================================================
// Main fused GEMM: y[128x128 tile] = A @ B^T.
// A[m, r*256+i] = e[m,r]*x[m,i] built on the fly (x/e in smem, hmul rescale).
// B fragments streamed straight from L2 (g_P) into registers: no B smem,
// no cp.async, NO barriers in the main loop -> warps run free.
// 8 warps 4Mx2N (warp tile 32x64), 2 CTAs/SM.
// ============================================================================
__global__ void __launch_bounds__(THREADS, 2)
LinearKG_main_kernel(const float* __restrict__ xg,
                     const float* __restrict__ eg,
                     float* __restrict__ out,
                     int n_nodes) {
    extern __shared__ __align__(1024) char smem[];
    const uint32_t sb = smem_u32(smem);
    const int tid = threadIdx.x;
    const int wid = tid >> 5;
    const int lid = tid & 31;
    const int row_base = blockIdx.x * M_TILE;
    const int o_base = blockIdx.y * N_TILE;
    const int warpM = (wid & 3) << 5;    // 0,32,64,96
    const int warpNh = wid >> 2;         // 0,1 -> 64-wide O half

    // ---- fill x tile (fp32 -> fp16, swizzled) + e tile; ONE sync ----
    {
        const float4* x4 = reinterpret_cast<const float4*>(xg);
        #pragma unroll
        for (int it = 0; it < 16; it++) {
            int v = tid + it * THREADS;          // 0..4095
            int row = v >> 5, c = v & 31;
            int gr = row_base + row;
            float4 f0 = make_float4(0.f, 0.f, 0.f, 0.f), f1 = f0;
            if (gr < n_nodes) {
                f0 = x4[(size_t)gr * 64 + c * 2];
                f1 = x4[(size_t)gr * 64 + c * 2 + 1];
            }
            __half2 h0 = __floats2half2_rn(f0.x, f0.y);
            __half2 h1 = __floats2half2_rn(f0.z, f0.w);
            __half2 h2 = __floats2half2_rn(f1.x, f1.y);
            __half2 h3 = __floats2half2_rn(f1.z, f1.w);
            uint4 u;
            u.x = *reinterpret_cast<uint32_t*>(&h0);
            u.y = *reinterpret_cast<uint32_t*>(&h1);
            u.z = *reinterpret_cast<uint32_t*>(&h2);
            u.w = *reinterpret_cast<uint32_t*>(&h3);
            *reinterpret_cast<uint4*>(smem + XOFF + row * 512 +
                                      ((c ^ (row & 7)) << 4)) = u;
        }
        __half* e2w = reinterpret_cast<__half*>(smem + E2OFF);
        #pragma unroll
        for (int it = 0; it < 16; it++) {
            int v = tid + it * THREADS;          // 0..4095
            int row = v >> 5, r = v & 31;
            int gr = row_base + row;
            float ev = (gr < n_nodes) ? eg[(size_t)gr * R_DIM + r] : 0.0f;
            e2w[row * 34 + r] = __float2half(ev);
        }
    }
    __syncthreads();   // the ONLY block-wide barrier before the epilogue

    const __half* e2h = reinterpret_cast<const __half*>(smem + E2OFF);

    // ---- A fragment addressing (identical to validated R4 scheme) ----
    const int g = lid >> 3;
    const int l7 = lid & 7;
    const int a_moff = (g & 1) * 8;
    const int a_koff = g >> 1;

    uint32_t aBase[2]; int aXor[2];
    #pragma unroll
    for (int mt = 0; mt < 2; mt++) {
        int mrow = warpM + mt * 16 + a_moff + l7;
        aBase[mt] = sb + XOFF + mrow * 512;
        aXor[mt] = mrow & 7;
    }
    const int frow = lid >> 2;
    const int fcol = (lid & 3) * 2;
    const int erow0 = (warpM + frow) * 34;
    const int erow1 = (warpM + 8 + frow) * 34;

    // ---- B fragment stream pointer (uint4 units), linear walk ----
    const int oh = blockIdx.y * 2 + warpNh;            // 0..3
    const uint4* __restrict__ pp = g_P + (size_t)oh * P_U4_PER_OH + lid;

    float acc[2][8][4];
    #pragma unroll
    for (int mt = 0; mt < 2; mt++)
        #pragma unroll
        for (int nt = 0; nt < 8; nt++)
            #pragma unroll
            for (int q = 0; q < 4; q++) acc[mt][nt][q] = 0.0f;

    uint32_t ez0[2], ez1[2];

    // prologue: prefetch B frags for (j=0, ks=0)
    uint4 nb0 = pp[0], nb1 = pp[32], nb2 = pp[64], nb3 = pp[96];
    pp += P_U4_PER_KS;

    // ---- main loop: 128 chunks, no barriers ----
    for (int j = 0; j < 128; j++) {
        const int r = j >> 2;
        if ((j & 3) == 0) {
            #pragma unroll
            for (int mt = 0; mt < 2; mt++) {
                __half h0 = e2h[erow0 + mt * 16 * 34 + r];
                __half h1 = e2h[erow1 + mt * 16 * 34 + r];
                __half2 p0 = __half2half2(h0);
                __half2 p1 = __half2half2(h1);
                ez0[mt] = *reinterpret_cast<uint32_t*>(&p0);
                ez1[mt] = *reinterpret_cast<uint32_t*>(&p1);
            }
        }
        const int kcA = (j & 3) * 8;
        #pragma unroll
        for (int ks = 0; ks < 4; ks++) {
            // consume current B frags, immediately prefetch next ks block
            uint4 c0 = nb0, c1 = nb1, c2 = nb2, c3 = nb3;
            nb0 = pp[0]; nb1 = pp[32]; nb2 = pp[64]; nb3 = pp[96];
            pp += P_U4_PER_KS;

            uint32_t a[2][4];
            #pragma unroll
            for (int mt = 0; mt < 2; mt++) {
                int kc = kcA + ks * 2 + a_koff;
                uint32_t ad = aBase[mt] + ((kc ^ aXor[mt]) << 4);
                LDSM_X4(a[mt][0], a[mt][1], a[mt][2], a[mt][3], ad);
                a[mt][0] = hmul2_u(a[mt][0], ez0[mt]);
                a[mt][1] = hmul2_u(a[mt][1], ez1[mt]);
                a[mt][2] = hmul2_u(a[mt][2], ez0[mt]);
                a[mt][3] = hmul2_u(a[mt][3], ez1[mt]);
            }
            #pragma unroll
            for (int mt = 0; mt < 2; mt++) {
                MMA16816(acc[mt][0], a[mt], c0.x, c0.y);
                MMA16816(acc[mt][1], a[mt], c0.z, c0.w);
                MMA16816(acc[mt][2], a[mt], c1.x, c1.y);
                MMA16816(acc[mt][3], a[mt], c1.z, c1.w);
                MMA16816(acc[mt][4], a[mt], c2.x, c2.y);
                MMA16816(acc[mt][5], a[mt], c2.z, c2.w);
                MMA16816(acc[mt][6], a[mt], c3.x, c3.y);
                MMA16816(acc[mt][7], a[mt], c3.z, c3.w);
            }
        }
    }

    // ---- bias chunk (j=128): A[m,k] = e[m,k], ksteps 0..1 ----
    {
        // ks=0 frags already prefetched in nb*; pp now points at (128, ks=1)
        #pragma unroll
        for (int ks = 0; ks < 2; ks++) {
            uint4 c0, c1, c2, c3;
            if (ks == 0) { c0 = nb0; c1 = nb1; c2 = nb2; c3 = nb3; }
            else         { c0 = pp[0]; c1 = pp[32]; c2 = pp[64]; c3 = pp[96]; }

            const int k0 = ks * 16 + fcol;
            uint32_t a[2][4];
            #pragma unroll
            for (int mt = 0; mt < 2; mt++) {
                a[mt][0] = *reinterpret_cast<const uint32_t*>(
                    e2h + erow0 + mt * 16 * 34 + k0);
                a[mt][1] = *reinterpret_cast<const uint32_t*>(
                    e2h + erow1 + mt * 16 * 34 + k0);
                a[mt][2] = *reinterpret_cast<const uint32_t*>(
                    e2h + erow0 + mt * 16 * 34 + k0 + 8);
                a[mt][3] = *reinterpret_cast<const uint32_t*>(
                    e2h + erow1 + mt * 16 * 34 + k0 + 8);
            }
            #pragma unroll
            for (int mt = 0; mt < 2; mt++) {
                MMA16816(acc[mt][0], a[mt], c0.x, c0.y);
                MMA16816(acc[mt][1], a[mt], c0.z, c0.w);
                MMA16816(acc[mt][2], a[mt], c1.x, c1.y);
                MMA16816(acc[mt][3], a[mt], c1.z, c1.w);
                MMA16816(acc[mt][4], a[mt], c2.x, c2.y);
                MMA16816(acc[mt][5], a[mt], c2.z, c2.w);
                MMA16816(acc[mt][6], a[mt], c3.x, c3.y);
                MMA16816(acc[mt][7], a[mt], c3.z, c3.w);
            }
        }
    }

    // ---- epilogue: store fp32 accumulators ----
    const int o_col0 = o_base + warpNh * 64;
    #pragma unroll
    for (int mt = 0; mt < 2; mt++) {
        int r0 = row_base + warpM + mt * 16 + frow;
        int r1 = r0 + 8;
        #pragma unroll
        for (int nt = 0; nt < 8; nt++) {
            int col = o_col0 + nt * 8 + fcol;
            if (r0 < n_nodes) {
                float2 v = make_float2(acc[mt][nt][0], acc[mt][nt][1]);
                *reinterpret_cast<float2*>(out + (size_t)r0 * O_DIM + col) = v;
            }
            if (r1 < n_nodes) {
                float2 v = make_float2(acc[mt][nt][2], acc[mt][nt][3]);
                *reinterpret_cast<float2*>(out + (size_t)r1 * O_DIM + col) = v;
            }
        }
    }
}

// ============================================================================
// Launch
// ============================================================================
extern "C" void kernel_launch(void* const* d_in, const int* in_sizes, int n_in,
                              void* d_out, int out_size) {
    const float* x = (const float*)d_in[0];   // [N, 256]
    const float* e = (const float*)d_in[1];   // [N, 32]
    const float* W = (const float*)d_in[2];   // [32, 256, 256]
    const float* b = (const float*)d_in[3];   // [32, 256]
    float* out = (float*)d_out;               // [N, 256]

    int n_nodes = in_sizes[0] / I_DIM;

    int prep_total = 4 * P_U4_PER_OH * 4;     // u32 elements
    LinearKG_prep_kernel<<<(prep_total + 255) / 256, 256>>>(W, b);

    cudaFuncSetAttribute(LinearKG_main_kernel,
                         cudaFuncAttributeMaxDynamicSharedMemorySize, SMEM_TOTAL);
    dim3 grid((n_nodes + M_TILE - 1) / M_TILE, O_DIM / N_TILE);
    LinearKG_main_kernel<<<grid, THREADS, SMEM_TOTAL>>>(x, e, out, n_nodes);
}